// round 1
// baseline (speedup 1.0000x reference)
#include <cuda_runtime.h>
#include <cuda_fp16.h>

#define NPTS      2097152
#define FEAT      32
#define PW        256   // plane width  (x/y/z resolution)
#define PH        128   // plane height (t resolution)
#define TEXELS    (PH * PW)            // 32768 per plane
#define U4_PER_TEXEL (FEAT / 8)        // 4 uint4 (8 halves each) per texel

// fp16 planes in [H, W, F] layout, stored as uint4 for aligned 16B vector access.
// 3 * 32768 * 4 * 16B = 6 MB device scratch (static, allowed).
__device__ uint4 g_planes4[3][TEXELS * U4_PER_TEXEL];

// ---------------------------------------------------------------------------
// Prologue: transpose [F, H, W] fp32 -> [H, W, F] fp16.
// One thread per (plane, texel). Reads are coalesced per f-iteration
// (consecutive lanes read consecutive yx). Writes: 4 x STG.128 per thread.
// ---------------------------------------------------------------------------
__global__ void transpose_planes_kernel(const float* __restrict__ p0,
                                        const float* __restrict__ p1,
                                        const float* __restrict__ p2) {
    int idx = blockIdx.x * blockDim.x + threadIdx.x;
    if (idx >= 3 * TEXELS) return;
    int plane = idx / TEXELS;
    int yx    = idx - plane * TEXELS;

    const float* src = (plane == 0) ? p0 : ((plane == 1) ? p1 : p2);

    __half buf[FEAT];
#pragma unroll
    for (int f = 0; f < FEAT; ++f) {
        buf[f] = __float2half(src[f * TEXELS + yx]);
    }
    const uint4* b4 = reinterpret_cast<const uint4*>(buf);
    uint4* dst = g_planes4[plane] + (size_t)yx * U4_PER_TEXEL;
#pragma unroll
    for (int k = 0; k < U4_PER_TEXEL; ++k) dst[k] = b4[k];
}

// ---------------------------------------------------------------------------
// Main: 4 threads per point; lane handles 8 features (one uint4 per corner).
// 12 x LDG.128 from L2-resident fp16 planes, fp32 bilinear math,
// 2 x STG.128 coalesced output.
// ---------------------------------------------------------------------------
__global__ void __launch_bounds__(256)
kplanes_sample_kernel(const float4* __restrict__ inp, float* __restrict__ out) {
    int tid = blockIdx.x * blockDim.x + threadIdx.x;
    int pt  = tid >> 2;
    int ln  = tid & 3;
    if (pt >= NPTS) return;

    float4 c = __ldg(inp + pt);

    // y coordinate (dim 3 == t) shared by all three planes. H = 128.
    float ty  = fminf(fmaxf((c.w + 1.0f) * 0.5f * (float)(PH - 1), 0.0f),
                      (float)(PH - 1));
    float y0f = floorf(ty);
    float wy  = ty - y0f;
    int   y0  = (int)y0f;
    int   y1  = min(y0 + 1, PH - 1);
    float omwy = 1.0f - wy;

    float acc[8];
#pragma unroll
    for (int j = 0; j < 8; ++j) acc[j] = 0.0f;

    float cxs[3] = {c.x, c.y, c.z};

#pragma unroll
    for (int p = 0; p < 3; ++p) {
        float tx  = fminf(fmaxf((cxs[p] + 1.0f) * 0.5f * (float)(PW - 1), 0.0f),
                          (float)(PW - 1));
        float x0f = floorf(tx);
        float wx  = tx - x0f;
        int   x0  = (int)x0f;
        int   x1  = min(x0 + 1, PW - 1);
        float omwx = 1.0f - wx;

        float w00 = omwx * omwy;
        float w01 = wx   * omwy;
        float w10 = omwx * wy;
        float w11 = wx   * wy;

        const uint4* base = g_planes4[p];
        uint4 v00 = __ldg(base + ((y0 * PW + x0) * U4_PER_TEXEL + ln));
        uint4 v01 = __ldg(base + ((y0 * PW + x1) * U4_PER_TEXEL + ln));
        uint4 v10 = __ldg(base + ((y1 * PW + x0) * U4_PER_TEXEL + ln));
        uint4 v11 = __ldg(base + ((y1 * PW + x1) * U4_PER_TEXEL + ln));

        const __half2* h00 = reinterpret_cast<const __half2*>(&v00);
        const __half2* h01 = reinterpret_cast<const __half2*>(&v01);
        const __half2* h10 = reinterpret_cast<const __half2*>(&v10);
        const __half2* h11 = reinterpret_cast<const __half2*>(&v11);

#pragma unroll
        for (int k = 0; k < 4; ++k) {
            float2 f00 = __half22float2(h00[k]);
            float2 f01 = __half22float2(h01[k]);
            float2 f10 = __half22float2(h10[k]);
            float2 f11 = __half22float2(h11[k]);
            acc[2 * k]     += f00.x * w00 + f01.x * w01 + f10.x * w10 + f11.x * w11;
            acc[2 * k + 1] += f00.y * w00 + f01.y * w01 + f10.y * w10 + f11.y * w11;
        }
    }

    float4* o = reinterpret_cast<float4*>(out + (size_t)pt * FEAT + ln * 8);
    o[0] = make_float4(acc[0], acc[1], acc[2], acc[3]);
    o[1] = make_float4(acc[4], acc[5], acc[6], acc[7]);
}

extern "C" void kernel_launch(void* const* d_in, const int* in_sizes, int n_in,
                              void* d_out, int out_size) {
    const float* inp = (const float*)d_in[0];
    const float* p0  = (const float*)d_in[1];
    const float* p1  = (const float*)d_in[2];
    const float* p2  = (const float*)d_in[3];
    float* out = (float*)d_out;

    {
        int total = 3 * TEXELS;
        int threads = 256;
        int blocks = (total + threads - 1) / threads;
        transpose_planes_kernel<<<blocks, threads>>>(p0, p1, p2);
    }
    {
        long long total = (long long)NPTS * 4;
        int threads = 256;
        int blocks = (int)((total + threads - 1) / threads);
        kplanes_sample_kernel<<<blocks, threads>>>((const float4*)inp, out);
    }
}

// round 4
// speedup vs baseline: 1.0190x; 1.0190x over previous
#include <cuda_runtime.h>
#include <cuda_fp16.h>

#define NPTS      2097152
#define FEAT      32
#define PW        256   // plane width  (x/y/z resolution)
#define PH        128   // plane height (t resolution)
#define TEXELS    (PH * PW)            // 32768 per plane
#define U4_PER_TEXEL (FEAT / 8)        // 4 uint4 (8 halves each) per texel

// fp16 planes in [H, W, F] layout, stored as uint4 for aligned 16B vector access.
// 3 * 32768 * 64B = 6 MB device scratch (static, allowed). L2-resident.
__device__ uint4 g_planes4[3][TEXELS * U4_PER_TEXEL];

// ---------------------------------------------------------------------------
// Prologue: transpose [F, H, W] fp32 -> [H, W, F] fp16.
// ---------------------------------------------------------------------------
__global__ void transpose_planes_kernel(const float* __restrict__ p0,
                                        const float* __restrict__ p1,
                                        const float* __restrict__ p2) {
    int idx = blockIdx.x * blockDim.x + threadIdx.x;
    if (idx >= 3 * TEXELS) return;
    int plane = idx / TEXELS;
    int yx    = idx - plane * TEXELS;

    const float* src = (plane == 0) ? p0 : ((plane == 1) ? p1 : p2);

    __half buf[FEAT];
#pragma unroll
    for (int f = 0; f < FEAT; ++f) {
        buf[f] = __float2half(src[f * TEXELS + yx]);
    }
    const uint4* b4 = reinterpret_cast<const uint4*>(buf);
    uint4* dst = g_planes4[plane] + (size_t)yx * U4_PER_TEXEL;
#pragma unroll
    for (int k = 0; k < U4_PER_TEXEL; ++k) dst[k] = b4[k];
}

// ---------------------------------------------------------------------------
// Main: 8 threads per point. Lanes 0-3 cover texel (y, x0), lanes 4-7 cover
// texel (y, x0+1) — one cooperative LDG.128 per row fetches the contiguous
// 128B texel pair (1 L1 line when x0 even, 2 when odd). 6 gather instructions
// per point instead of 12. Sides merged with one shfl_xor(4) reduction.
// Border handling: clamp x0 <= W-2 and fold the boundary into wx (identical
// result to reference's x1=min(x0+1,W-1) formulation).
// ---------------------------------------------------------------------------
__global__ void __launch_bounds__(256)
kplanes_sample_kernel(const float4* __restrict__ inp, float* __restrict__ out) {
    int tid  = blockIdx.x * blockDim.x + threadIdx.x;
    int pt   = tid >> 3;
    int ln   = tid & 7;
    int side = ln >> 2;            // 0: x0-side, 1: x1-side
    if (pt >= NPTS) return;

    float4 c = __ldg(inp + pt);

    // y coordinate (t, dim 3) shared by all three planes. H = 128.
    float ty   = fminf(fmaxf((c.w + 1.0f) * 0.5f * (float)(PH - 1), 0.0f),
                       (float)(PH - 1));
    int   y0   = min((int)ty, PH - 2);
    float wy   = ty - (float)y0;
    float omwy = 1.0f - wy;

    float acc[8];
#pragma unroll
    for (int j = 0; j < 8; ++j) acc[j] = 0.0f;

    float cxs[3] = {c.x, c.y, c.z};

#pragma unroll
    for (int p = 0; p < 3; ++p) {
        float tx = fminf(fmaxf((cxs[p] + 1.0f) * 0.5f * (float)(PW - 1), 0.0f),
                         (float)(PW - 1));
        int   x0 = min((int)tx, PW - 2);
        float wx = tx - (float)x0;
        // lane-side x-weight: lanes 0-3 get (1-wx), lanes 4-7 get wx
        float wside = side ? wx : (1.0f - wx);
        float w0 = wside * omwy;   // row y0 weight
        float w1 = wside * wy;     // row y1 weight

        const uint4* base = g_planes4[p]
                          + (size_t)(y0 * PW + x0) * U4_PER_TEXEL + ln;
        uint4 r0 = __ldg(base);
        uint4 r1 = __ldg(base + PW * U4_PER_TEXEL);

        const __half2* h0 = reinterpret_cast<const __half2*>(&r0);
        const __half2* h1 = reinterpret_cast<const __half2*>(&r1);
#pragma unroll
        for (int k = 0; k < 4; ++k) {
            float2 f0 = __half22float2(h0[k]);
            float2 f1 = __half22float2(h1[k]);
            acc[2 * k]     += f0.x * w0 + f1.x * w1;
            acc[2 * k + 1] += f0.y * w0 + f1.y * w1;
        }
    }

    // Merge x0-side (lanes 0-3) with x1-side (lanes 4-7).
#pragma unroll
    for (int j = 0; j < 8; ++j)
        acc[j] += __shfl_xor_sync(0xffffffffu, acc[j], 4);

    // Lane ln owns feature block (ln&3): features (ln&3)*8 .. +7.
    // side 0 writes floats [0..3] of the block, side 1 writes [4..7].
    float* o = out + (size_t)pt * FEAT + (ln & 3) * 8 + side * 4;
    int b = side * 4;
    *reinterpret_cast<float4*>(o) =
        make_float4(acc[b + 0], acc[b + 1], acc[b + 2], acc[b + 3]);
}

extern "C" void kernel_launch(void* const* d_in, const int* in_sizes, int n_in,
                              void* d_out, int out_size) {
    const float* inp = (const float*)d_in[0];
    const float* p0  = (const float*)d_in[1];
    const float* p1  = (const float*)d_in[2];
    const float* p2  = (const float*)d_in[3];
    float* out = (float*)d_out;

    {
        int total = 3 * TEXELS;
        int threads = 256;
        int blocks = (total + threads - 1) / threads;
        transpose_planes_kernel<<<blocks, threads>>>(p0, p1, p2);
    }
    {
        long long total = (long long)NPTS * 8;
        int threads = 256;
        int blocks = (int)((total + threads - 1) / threads);
        kplanes_sample_kernel<<<blocks, threads>>>((const float4*)inp, out);
    }
}

// round 8
// speedup vs baseline: 1.3146x; 1.2901x over previous
#include <cuda_runtime.h>
#include <cuda_fp16.h>

#define NPTS      2097152
#define FEAT      32
#define PW        256   // plane width  (x/y/z resolution)
#define PH        128   // plane height (t resolution)
#define TEXELS    (PH * PW)            // 32768 per plane
#define U4_PER_TEXEL (FEAT / 8)        // 4 uint4 (8 halves each) per texel

// fp16 planes in [H, W, F] layout, stored as uint4 for aligned 16B vector access.
// 3 * 32768 * 64B = 6 MB device scratch (static, allowed). L2-resident.
__device__ uint4 g_planes4[3][TEXELS * U4_PER_TEXEL];

// ---------------------------------------------------------------------------
// Prologue: transpose [F, H, W] fp32 -> [H, W, F] fp16.
// ---------------------------------------------------------------------------
__global__ void transpose_planes_kernel(const float* __restrict__ p0,
                                        const float* __restrict__ p1,
                                        const float* __restrict__ p2) {
    int idx = blockIdx.x * blockDim.x + threadIdx.x;
    if (idx >= 3 * TEXELS) return;
    int plane = idx / TEXELS;
    int yx    = idx - plane * TEXELS;

    const float* src = (plane == 0) ? p0 : ((plane == 1) ? p1 : p2);

    __half buf[FEAT];
#pragma unroll
    for (int f = 0; f < FEAT; ++f) {
        buf[f] = __float2half(src[f * TEXELS + yx]);
    }
    const uint4* b4 = reinterpret_cast<const uint4*>(buf);
    uint4* dst = g_planes4[plane] + (size_t)yx * U4_PER_TEXEL;
#pragma unroll
    for (int k = 0; k < U4_PER_TEXEL; ++k) dst[k] = b4[k];
}

// ---------------------------------------------------------------------------
// Main: 8 threads per point. Lanes 0-3 cover texel (y, x0), lanes 4-7 cover
// texel (y, x0+1) via one cooperative LDG.128 per row (contiguous 128B pair).
// Bilinear weighting done with HFMA2 in half2 (2 instr per uint4 instead of
// 8 cvt + 16 FFMA), merged across sides with 4 shfl + 4 HADD2. Each lane
// converts only the 2 half2 it stores.
// ---------------------------------------------------------------------------
__global__ void __launch_bounds__(256)
kplanes_sample_kernel(const float4* __restrict__ inp, float* __restrict__ out) {
    int tid  = blockIdx.x * blockDim.x + threadIdx.x;
    int pt   = tid >> 3;
    int ln   = tid & 7;
    int side = ln >> 2;            // 0: x0-side, 1: x1-side
    if (pt >= NPTS) return;

    float4 c = __ldg(inp + pt);

    // y coordinate (t, dim 3) shared by all three planes. H = 128.
    float ty   = fminf(fmaxf((c.w + 1.0f) * 0.5f * (float)(PH - 1), 0.0f),
                       (float)(PH - 1));
    int   y0   = min((int)ty, PH - 2);
    float wy   = ty - (float)y0;
    float omwy = 1.0f - wy;
    float sbase = (float)(1 - side);   // |sbase - wx| = side ? wx : 1-wx

    __half2 acc[4];
#pragma unroll
    for (int j = 0; j < 4; ++j) acc[j] = __float2half2_rn(0.0f);

    float cxs[3] = {c.x, c.y, c.z};
    int rowoff = y0 * PW * U4_PER_TEXEL + ln;

#pragma unroll
    for (int p = 0; p < 3; ++p) {
        float tx = fminf(fmaxf((cxs[p] + 1.0f) * 0.5f * (float)(PW - 1), 0.0f),
                         (float)(PW - 1));
        int   x0 = min((int)tx, PW - 2);
        float wx = tx - (float)x0;
        float wside = fabsf(sbase - wx);
        __half2 w0 = __float2half2_rn(wside * omwy);   // row y0 weight
        __half2 w1 = __float2half2_rn(wside * wy);     // row y1 weight

        const uint4* base = g_planes4[p] + rowoff + x0 * U4_PER_TEXEL;
        uint4 r0 = __ldg(base);
        uint4 r1 = __ldg(base + PW * U4_PER_TEXEL);

        const __half2* h0 = reinterpret_cast<const __half2*>(&r0);
        const __half2* h1 = reinterpret_cast<const __half2*>(&r1);
#pragma unroll
        for (int k = 0; k < 4; ++k) {
            acc[k] = __hfma2(h1[k], w1, acc[k]);
            acc[k] = __hfma2(h0[k], w0, acc[k]);
        }
    }

    // Merge x0-side (lanes 0-3) with x1-side (lanes 4-7) in half2.
#pragma unroll
    for (int j = 0; j < 4; ++j) {
        unsigned u = __shfl_xor_sync(0xffffffffu,
                                     *reinterpret_cast<unsigned*>(&acc[j]), 4);
        acc[j] = __hadd2(acc[j], *reinterpret_cast<__half2*>(&u));
    }

    // Lane ln owns feature block (ln&3): features (ln&3)*8 .. +7.
    // side 0 stores acc[0..1] (floats 0..3), side 1 stores acc[2..3].
    float2 fa = __half22float2(acc[side * 2 + 0]);
    float2 fb = __half22float2(acc[side * 2 + 1]);
    float* o = out + (size_t)pt * FEAT + (ln & 3) * 8 + side * 4;
    *reinterpret_cast<float4*>(o) = make_float4(fa.x, fa.y, fb.x, fb.y);
}

extern "C" void kernel_launch(void* const* d_in, const int* in_sizes, int n_in,
                              void* d_out, int out_size) {
    const float* inp = (const float*)d_in[0];
    const float* p0  = (const float*)d_in[1];
    const float* p1  = (const float*)d_in[2];
    const float* p2  = (const float*)d_in[3];
    float* out = (float*)d_out;

    {
        int total = 3 * TEXELS;
        int threads = 256;
        int blocks = (total + threads - 1) / threads;
        transpose_planes_kernel<<<blocks, threads>>>(p0, p1, p2);
    }
    {
        long long total = (long long)NPTS * 8;
        int threads = 256;
        int blocks = (int)((total + threads - 1) / threads);
        kplanes_sample_kernel<<<blocks, threads>>>((const float4*)inp, out);
    }
}

// round 10
// speedup vs baseline: 1.4128x; 1.0746x over previous
#include <cuda_runtime.h>
#include <cuda_fp16.h>

#define NPTS      2097152
#define FEAT      32
#define PW        256   // plane width  (x/y/z resolution)
#define PH        128   // plane height (t resolution)
#define TEXELS    (PH * PW)            // 32768 per plane

// Pair-replicated fp16 layout: for each (plane, y, x0) one 128B line holding
// [texel(y,x0) | texel(y,min(x0+1,PW-1))], 16 halves per texel.
// Any bilinear x-pair is exactly ONE fully-used, 128B-aligned L1 line.
// 3 * 32768 * 128B = 12.6 MB static scratch; L2-resident.
struct __align__(128) Line128 { uint4 v[8]; };
__device__ Line128 g_pairs[3 * TEXELS];

// ---------------------------------------------------------------------------
// Prologue: build pair-replicated fp16 lines from [F, H, W] fp32 planes.
// One thread per (plane, y, x0). Lane-consecutive x0 -> coalesced reads.
// ---------------------------------------------------------------------------
__global__ void build_pairs_kernel(const float* __restrict__ p0,
                                   const float* __restrict__ p1,
                                   const float* __restrict__ p2) {
    int idx = blockIdx.x * blockDim.x + threadIdx.x;
    if (idx >= 3 * TEXELS) return;
    int plane = idx / TEXELS;
    int yx    = idx - plane * TEXELS;
    int x0    = yx & (PW - 1);
    int x1    = min(x0 + 1, PW - 1);
    int yx1   = yx - x0 + x1;

    const float* src = (plane == 0) ? p0 : ((plane == 1) ? p1 : p2);

    __half buf[2 * FEAT];
#pragma unroll
    for (int f = 0; f < FEAT; ++f) {
        buf[f]        = __float2half(src[f * TEXELS + yx]);
        buf[FEAT + f] = __float2half(src[f * TEXELS + yx1]);
    }
    const uint4* b4 = reinterpret_cast<const uint4*>(buf);
    Line128& dst = g_pairs[idx];
#pragma unroll
    for (int k = 0; k < 8; ++k) dst.v[k] = b4[k];
}

// ---------------------------------------------------------------------------
// Main: 8 threads per point. The 8 lanes cooperatively load one Line128 per
// (plane, row): lanes 0-3 see texel x0, lanes 4-7 see texel x0+1. Six loads
// per point, each exactly one L1 wavefront. HFMA2 weighting, shfl_xor(4)
// side-merge in half2, fp32 convert only at the store.
// ---------------------------------------------------------------------------
__global__ void __launch_bounds__(256)
kplanes_sample_kernel(const float4* __restrict__ inp, float* __restrict__ out) {
    int tid  = blockIdx.x * blockDim.x + threadIdx.x;
    int pt   = tid >> 3;
    int ln   = tid & 7;
    int side = ln >> 2;            // 0: x0-side, 1: x1-side
    if (pt >= NPTS) return;

    float4 c = __ldg(inp + pt);

    // y coordinate (t, dim 3) shared by all three planes. H = 128.
    float ty   = fminf(fmaxf((c.w + 1.0f) * 0.5f * (float)(PH - 1), 0.0f),
                       (float)(PH - 1));
    int   y0   = min((int)ty, PH - 2);
    float wy   = ty - (float)y0;
    float omwy = 1.0f - wy;
    float sbase = (float)(1 - side);   // |sbase - wx| = side ? wx : 1-wx

    __half2 acc[4];
#pragma unroll
    for (int j = 0; j < 4; ++j) acc[j] = __float2half2_rn(0.0f);

    float cxs[3] = {c.x, c.y, c.z};
    int row0 = y0 * PW;

#pragma unroll
    for (int p = 0; p < 3; ++p) {
        float tx = fminf(fmaxf((cxs[p] + 1.0f) * 0.5f * (float)(PW - 1), 0.0f),
                         (float)(PW - 1));
        int   x0 = min((int)tx, PW - 2);
        float wx = tx - (float)x0;
        float wside = fabsf(sbase - wx);
        __half2 w0 = __float2half2_rn(wside * omwy);   // row y0 weight
        __half2 w1 = __float2half2_rn(wside * wy);     // row y1 weight

        const Line128* base = g_pairs + (p * TEXELS + row0 + x0);
        uint4 r0 = __ldg(&base->v[ln]);
        uint4 r1 = __ldg(&(base + PW)->v[ln]);

        const __half2* h0 = reinterpret_cast<const __half2*>(&r0);
        const __half2* h1 = reinterpret_cast<const __half2*>(&r1);
#pragma unroll
        for (int k = 0; k < 4; ++k) {
            acc[k] = __hfma2(h1[k], w1, acc[k]);
            acc[k] = __hfma2(h0[k], w0, acc[k]);
        }
    }

    // Merge x0-side (lanes 0-3) with x1-side (lanes 4-7) in half2.
#pragma unroll
    for (int j = 0; j < 4; ++j) {
        unsigned u = __shfl_xor_sync(0xffffffffu,
                                     *reinterpret_cast<unsigned*>(&acc[j]), 4);
        acc[j] = __hadd2(acc[j], *reinterpret_cast<__half2*>(&u));
    }

    // Lane ln owns feature block (ln&3): features (ln&3)*8 .. +7.
    // side 0 stores acc[0..1] (floats 0..3), side 1 stores acc[2..3].
    float2 fa = __half22float2(acc[side * 2 + 0]);
    float2 fb = __half22float2(acc[side * 2 + 1]);
    float* o = out + (size_t)pt * FEAT + (ln & 3) * 8 + side * 4;
    *reinterpret_cast<float4*>(o) = make_float4(fa.x, fa.y, fb.x, fb.y);
}

extern "C" void kernel_launch(void* const* d_in, const int* in_sizes, int n_in,
                              void* d_out, int out_size) {
    const float* inp = (const float*)d_in[0];
    const float* p0  = (const float*)d_in[1];
    const float* p1  = (const float*)d_in[2];
    const float* p2  = (const float*)d_in[3];
    float* out = (float*)d_out;

    {
        int total = 3 * TEXELS;
        int threads = 256;
        int blocks = (total + threads - 1) / threads;
        build_pairs_kernel<<<blocks, threads>>>(p0, p1, p2);
    }
    {
        long long total = (long long)NPTS * 8;
        int threads = 256;
        int blocks = (int)((total + threads - 1) / threads);
        kplanes_sample_kernel<<<blocks, threads>>>((const float4*)inp, out);
    }
}

// round 11
// speedup vs baseline: 1.4312x; 1.0131x over previous
#include <cuda_runtime.h>
#include <cuda_fp16.h>

#define NPTS      2097152
#define FEAT      32
#define PW        256   // plane width  (x/y/z resolution)
#define PH        128   // plane height (t resolution)
#define TEXELS    (PH * PW)            // 32768 per plane

// Pair-replicated fp16 layout: for each (plane, y, x0) one 128B line holding
// [texel(y,x0) | texel(y,min(x0+1,PW-1))], 16 halves per texel.
// Any bilinear x-pair is exactly ONE fully-used, 128B-aligned L1 line.
// 3 * 32768 * 128B = 12.6 MB static scratch; L2-resident.
struct __align__(128) Line128 { uint4 v[8]; };
__device__ Line128 g_pairs[3 * TEXELS];

// ---------------------------------------------------------------------------
// Prologue: build pair-replicated fp16 lines from [F, H, W] fp32 planes.
// ---------------------------------------------------------------------------
__global__ void build_pairs_kernel(const float* __restrict__ p0,
                                   const float* __restrict__ p1,
                                   const float* __restrict__ p2) {
    int idx = blockIdx.x * blockDim.x + threadIdx.x;
    if (idx >= 3 * TEXELS) return;
    int plane = idx / TEXELS;
    int yx    = idx - plane * TEXELS;
    int x0    = yx & (PW - 1);
    int x1    = min(x0 + 1, PW - 1);
    int yx1   = yx - x0 + x1;

    const float* src = (plane == 0) ? p0 : ((plane == 1) ? p1 : p2);

    __half buf[2 * FEAT];
#pragma unroll
    for (int f = 0; f < FEAT; ++f) {
        buf[f]        = __float2half(src[f * TEXELS + yx]);
        buf[FEAT + f] = __float2half(src[f * TEXELS + yx1]);
    }
    const uint4* b4 = reinterpret_cast<const uint4*>(buf);
    Line128& dst = g_pairs[idx];
#pragma unroll
    for (int k = 0; k < 8; ++k) dst.v[k] = b4[k];
}

// ---------------------------------------------------------------------------
// Main: 8 threads per point, lanes 0-3 = texel x0, lanes 4-7 = texel x0+1.
// Restructured for MLP: all coordinates/weights/addresses computed first,
// then ALL SIX gather LDG.128 issued back-to-back (6 outstanding loads per
// lane hides the ~250cyc L2-hit latency), then 24 HFMA2, shfl merge, store.
// ---------------------------------------------------------------------------
__global__ void __launch_bounds__(256)
kplanes_sample_kernel(const float4* __restrict__ inp, float* __restrict__ out) {
    int tid  = blockIdx.x * blockDim.x + threadIdx.x;
    int pt   = tid >> 3;
    int ln   = tid & 7;
    int side = ln >> 2;            // 0: x0-side, 1: x1-side
    if (pt >= NPTS) return;

    float4 c = __ldg(inp + pt);

    // y coordinate (t, dim 3) shared by all three planes. H = 128.
    // saturate-folded clamp: identical to clip((c+1)*0.5*(H-1), 0, H-1).
    float ty   = __saturatef(__fmaf_rn(c.w, 0.5f, 0.5f)) * (float)(PH - 1);
    int   y0   = min((int)ty, PH - 2);
    float wy   = ty - (float)y0;
    float omwy = 1.0f - wy;
    float sbase = (float)(1 - side);   // |sbase - wx| = side ? wx : 1-wx

    float cxs[3] = {c.x, c.y, c.z};

    // ---- Phase 1: all coords, weights, addresses ----
    __half2 w0[3], w1[3];
    const uint4* addr[3];
    const char* base_row = reinterpret_cast<const char*>(g_pairs)
                         + (size_t)(y0 * PW) * sizeof(Line128)
                         + (size_t)ln * sizeof(uint4);
#pragma unroll
    for (int p = 0; p < 3; ++p) {
        float tx = __saturatef(__fmaf_rn(cxs[p], 0.5f, 0.5f)) * (float)(PW - 1);
        int   x0 = min((int)tx, PW - 2);
        float wx = tx - (float)x0;
        float wside = fabsf(sbase - wx);
        w0[p] = __float2half2_rn(wside * omwy);   // row y0 weight
        w1[p] = __float2half2_rn(wside * wy);     // row y1 weight
        addr[p] = reinterpret_cast<const uint4*>(
            base_row + (size_t)(p * TEXELS + x0) * sizeof(Line128));
    }

    // ---- Phase 2: issue all 6 gathers back-to-back (MLP=6) ----
    uint4 r0[3], r1[3];
#pragma unroll
    for (int p = 0; p < 3; ++p) {
        r0[p] = __ldg(addr[p]);
        r1[p] = __ldg(addr[p] + PW * 8);   // +PW Line128s = next row
    }

    // ---- Phase 3: weighting in half2 ----
    __half2 acc[4];
#pragma unroll
    for (int j = 0; j < 4; ++j) acc[j] = __float2half2_rn(0.0f);

#pragma unroll
    for (int p = 0; p < 3; ++p) {
        const __half2* h0 = reinterpret_cast<const __half2*>(&r0[p]);
        const __half2* h1 = reinterpret_cast<const __half2*>(&r1[p]);
#pragma unroll
        for (int k = 0; k < 4; ++k) {
            acc[k] = __hfma2(h1[k], w1[p], acc[k]);
            acc[k] = __hfma2(h0[k], w0[p], acc[k]);
        }
    }

    // Merge x0-side (lanes 0-3) with x1-side (lanes 4-7) in half2.
#pragma unroll
    for (int j = 0; j < 4; ++j) {
        unsigned u = __shfl_xor_sync(0xffffffffu,
                                     *reinterpret_cast<unsigned*>(&acc[j]), 4);
        acc[j] = __hadd2(acc[j], *reinterpret_cast<__half2*>(&u));
    }

    // Lane ln owns feature block (ln&3): features (ln&3)*8 .. +7.
    // side 0 stores acc[0..1] (floats 0..3), side 1 stores acc[2..3].
    float2 fa = __half22float2(acc[side * 2 + 0]);
    float2 fb = __half22float2(acc[side * 2 + 1]);
    float* o = out + (size_t)pt * FEAT + (ln & 3) * 8 + side * 4;
    *reinterpret_cast<float4*>(o) = make_float4(fa.x, fa.y, fb.x, fb.y);
}

extern "C" void kernel_launch(void* const* d_in, const int* in_sizes, int n_in,
                              void* d_out, int out_size) {
    const float* inp = (const float*)d_in[0];
    const float* p0  = (const float*)d_in[1];
    const float* p1  = (const float*)d_in[2];
    const float* p2  = (const float*)d_in[3];
    float* out = (float*)d_out;

    {
        int total = 3 * TEXELS;
        int threads = 256;
        int blocks = (total + threads - 1) / threads;
        build_pairs_kernel<<<blocks, threads>>>(p0, p1, p2);
    }
    {
        long long total = (long long)NPTS * 8;
        int threads = 256;
        int blocks = (int)((total + threads - 1) / threads);
        kplanes_sample_kernel<<<blocks, threads>>>((const float4*)inp, out);
    }
}

// round 12
// speedup vs baseline: 1.4687x; 1.0262x over previous
#include <cuda_runtime.h>
#include <cuda_fp16.h>

#define NPTS      2097152
#define FEAT      32
#define PW        256   // plane width  (x/y/z resolution)
#define PH        128   // plane height (t resolution)
#define TEXELS    (PH * PW)            // 32768 per plane

// Pair-replicated fp16 layout: for each (plane, y, x0) one 128B line holding
// [texel(y,x0) | texel(y,min(x0+1,PW-1))], 16 halves per texel.
// Any bilinear x-pair is exactly ONE fully-used, 128B-aligned L1 line.
// 3 * 32768 * 128B = 12.6 MB static scratch; L2-resident.
struct __align__(128) Line128 { uint4 v[8]; };
__device__ Line128 g_pairs[3 * TEXELS];

// ---------------------------------------------------------------------------
// Prologue: build pair-replicated fp16 lines from [F, H, W] fp32 planes.
// ---------------------------------------------------------------------------
__global__ void build_pairs_kernel(const float* __restrict__ p0,
                                   const float* __restrict__ p1,
                                   const float* __restrict__ p2) {
    int idx = blockIdx.x * blockDim.x + threadIdx.x;
    if (idx >= 3 * TEXELS) return;
    int plane = idx / TEXELS;
    int yx    = idx - plane * TEXELS;
    int x0    = yx & (PW - 1);
    int x1    = min(x0 + 1, PW - 1);
    int yx1   = yx - x0 + x1;

    const float* src = (plane == 0) ? p0 : ((plane == 1) ? p1 : p2);

    __half buf[2 * FEAT];
#pragma unroll
    for (int f = 0; f < FEAT; ++f) {
        buf[f]        = __float2half(src[f * TEXELS + yx]);
        buf[FEAT + f] = __float2half(src[f * TEXELS + yx1]);
    }
    const uint4* b4 = reinterpret_cast<const uint4*>(buf);
    Line128& dst = g_pairs[idx];
#pragma unroll
    for (int k = 0; k < 8; ++k) dst.v[k] = b4[k];
}

// ---------------------------------------------------------------------------
// Per-point helpers (forceinline). 8 lanes per point; lanes 0-3 = texel x0,
// lanes 4-7 = texel x0+1 of the pair-replicated 128B line.
// ---------------------------------------------------------------------------
struct PtState {
    uint4   r0[3], r1[3];       // in-flight gather results (rows y0, y1)
    __half2 w0[3], w1[3];       // per-plane lane weights
};

__device__ __forceinline__ void issue_point(const float4& c, int ln, float sbase,
                                            const char* gbase, PtState& s) {
    // y coordinate (t, dim 3) shared by all three planes. H = 128.
    float ty   = __saturatef(__fmaf_rn(c.w, 0.5f, 0.5f)) * (float)(PH - 1);
    int   y0   = min((int)ty, PH - 2);
    float wy   = ty - (float)y0;
    float omwy = 1.0f - wy;

    unsigned rowoff = ((unsigned)(y0 * PW) << 7) + ((unsigned)ln << 4);
    float cxs[3] = {c.x, c.y, c.z};

#pragma unroll
    for (int p = 0; p < 3; ++p) {
        float tx = __saturatef(__fmaf_rn(cxs[p], 0.5f, 0.5f)) * (float)(PW - 1);
        int   x0 = min((int)tx, PW - 2);
        float wx = tx - (float)x0;
        float wside = fabsf(sbase - wx);
        s.w0[p] = __float2half2_rn(wside * omwy);
        s.w1[p] = __float2half2_rn(wside * wy);

        const char* a = gbase + ((size_t)p * (TEXELS * 128))
                              + (rowoff + ((unsigned)x0 << 7));
        s.r0[p] = __ldg(reinterpret_cast<const uint4*>(a));
        s.r1[p] = __ldg(reinterpret_cast<const uint4*>(a + PW * 128));
    }
}

__device__ __forceinline__ void consume_point(const PtState& s, int ln, int side,
                                              float* __restrict__ out, int pt) {
    __half2 acc[4];
#pragma unroll
    for (int j = 0; j < 4; ++j) acc[j] = __float2half2_rn(0.0f);

#pragma unroll
    for (int p = 0; p < 3; ++p) {
        const __half2* h0 = reinterpret_cast<const __half2*>(&s.r0[p]);
        const __half2* h1 = reinterpret_cast<const __half2*>(&s.r1[p]);
#pragma unroll
        for (int k = 0; k < 4; ++k) {
            acc[k] = __hfma2(h1[k], s.w1[p], acc[k]);
            acc[k] = __hfma2(h0[k], s.w0[p], acc[k]);
        }
    }

    // Merge x0-side (lanes 0-3) with x1-side (lanes 4-7) in half2.
#pragma unroll
    for (int j = 0; j < 4; ++j) {
        unsigned u = __shfl_xor_sync(0xffffffffu,
                                     *reinterpret_cast<const unsigned*>(&acc[j]), 4);
        acc[j] = __hadd2(acc[j], *reinterpret_cast<__half2*>(&u));
    }

    float2 fa = __half22float2(acc[side * 2 + 0]);
    float2 fb = __half22float2(acc[side * 2 + 1]);
    float* o = out + (size_t)pt * FEAT + (ln & 3) * 8 + side * 4;
    *reinterpret_cast<float4*>(o) = make_float4(fa.x, fa.y, fb.x, fb.y);
}

// ---------------------------------------------------------------------------
// Main: 2 points per 8-lane group, software-pipelined. Both points' 12
// gathers are issued before either consume, forcing ptxas to keep 12 uint4
// in flight (MLP ~12) so the ~250cyc L2-hit latency overlaps pt1's coord
// math and pt0's weighting math.
// ---------------------------------------------------------------------------
__global__ void __launch_bounds__(256)
kplanes_sample_kernel(const float4* __restrict__ inp, float* __restrict__ out) {
    int tid  = blockIdx.x * blockDim.x + threadIdx.x;
    int g    = tid >> 3;
    int ln   = tid & 7;
    int side = ln >> 2;
    float sbase = (float)(1 - side);
    int pt0 = g * 2;
    if (pt0 >= NPTS) return;
    int pt1 = pt0 + 1;

    const char* gbase = reinterpret_cast<const char*>(g_pairs);

    float4 c0 = __ldg(inp + pt0);
    float4 c1 = __ldg(inp + pt1);

    PtState s0, s1;
    issue_point(c0, ln, sbase, gbase, s0);
    issue_point(c1, ln, sbase, gbase, s1);
    consume_point(s0, ln, side, out, pt0);
    consume_point(s1, ln, side, out, pt1);
}

extern "C" void kernel_launch(void* const* d_in, const int* in_sizes, int n_in,
                              void* d_out, int out_size) {
    const float* inp = (const float*)d_in[0];
    const float* p0  = (const float*)d_in[1];
    const float* p1  = (const float*)d_in[2];
    const float* p2  = (const float*)d_in[3];
    float* out = (float*)d_out;

    {
        int total = 3 * TEXELS;
        int threads = 256;
        int blocks = (total + threads - 1) / threads;
        build_pairs_kernel<<<blocks, threads>>>(p0, p1, p2);
    }
    {
        long long total = (long long)NPTS * 8 / 2;   // 8 lanes, 2 points/group
        int threads = 256;
        int blocks = (int)((total + threads - 1) / threads);
        kplanes_sample_kernel<<<blocks, threads>>>((const float4*)inp, out);
    }
}

// round 14
// speedup vs baseline: 1.5757x; 1.0729x over previous
#include <cuda_runtime.h>
#include <cuda_fp16.h>

#define NPTS      2097152
#define FEAT      32
#define PW        256   // plane width  (x/y/z resolution)
#define PH        128   // plane height (t resolution)
#define TEXELS    (PH * PW)            // 32768 per plane

// Pair-replicated fp16 layout: for each (plane, y, x0) one 128B line holding
// [texel(y,x0) | texel(y,min(x0+1,PW-1))], 16 halves per texel.
// Any bilinear x-pair is exactly ONE fully-used, 128B-aligned L1 line.
// 3 * 32768 * 128B = 12.6 MB static scratch; L2-resident.
struct __align__(128) Line128 { uint4 v[8]; };
__device__ Line128 g_pairs[3 * TEXELS];

// ---------------------------------------------------------------------------
// Prologue: build pair-replicated fp16 lines from [F, H, W] fp32 planes.
// ---------------------------------------------------------------------------
__global__ void build_pairs_kernel(const float* __restrict__ p0,
                                   const float* __restrict__ p1,
                                   const float* __restrict__ p2) {
    int idx = blockIdx.x * blockDim.x + threadIdx.x;
    if (idx >= 3 * TEXELS) return;
    int plane = idx / TEXELS;
    int yx    = idx - plane * TEXELS;
    int x0    = yx & (PW - 1);
    int x1    = min(x0 + 1, PW - 1);
    int yx1   = yx - x0 + x1;

    const float* src = (plane == 0) ? p0 : ((plane == 1) ? p1 : p2);

    __half buf[2 * FEAT];
#pragma unroll
    for (int f = 0; f < FEAT; ++f) {
        buf[f]        = __float2half(src[f * TEXELS + yx]);
        buf[FEAT + f] = __float2half(src[f * TEXELS + yx1]);
    }
    const uint4* b4 = reinterpret_cast<const uint4*>(buf);
    Line128& dst = g_pairs[idx];
#pragma unroll
    for (int k = 0; k < 8; ++k) dst.v[k] = b4[k];
}

// Volatile v4 load: ptxas cannot reorder/sink this, pinning the batched
// load schedule (true MLP) regardless of register-pressure heuristics.
__device__ __forceinline__ uint4 ldg_v4_pinned(const char* p) {
    uint4 r;
    asm volatile("ld.global.nc.v4.u32 {%0,%1,%2,%3}, [%4];"
                 : "=r"(r.x), "=r"(r.y), "=r"(r.z), "=r"(r.w)
                 : "l"(p));
    return r;
}

// ---------------------------------------------------------------------------
// Per-point state: gather results + raw interpolation fractions.
// Weights are materialized AFTER the loads issue (cvt work hides under
// memory latency; only wx[3], wy floats live across the loads).
// ---------------------------------------------------------------------------
struct PtState {
    uint4 r0[3], r1[3];
    float wx[3];
    float wy;
};

__device__ __forceinline__ void issue_point(const float4& c, unsigned lnoff,
                                            const char* gbase, PtState& s) {
    float ty = __saturatef(__fmaf_rn(c.w, 0.5f, 0.5f)) * (float)(PH - 1);
    int   y0 = min((int)ty, PH - 2);
    s.wy     = ty - (float)y0;

    unsigned rowoff = ((unsigned)(y0 * PW) << 7) + lnoff;
    float cxs[3] = {c.x, c.y, c.z};

#pragma unroll
    for (int p = 0; p < 3; ++p) {
        float tx = __saturatef(__fmaf_rn(cxs[p], 0.5f, 0.5f)) * (float)(PW - 1);
        int   x0 = min((int)tx, PW - 2);
        s.wx[p]  = tx - (float)x0;
        const char* a = gbase + ((size_t)p * (TEXELS * 128))
                              + (rowoff + ((unsigned)x0 << 7));
        s.r0[p] = ldg_v4_pinned(a);
        s.r1[p] = ldg_v4_pinned(a + PW * 128);
    }
}

__device__ __forceinline__ void consume_point(const PtState& s, int ln, int side,
                                              float sbase,
                                              float* __restrict__ out, int pt) {
    float omwy = 1.0f - s.wy;
    __half2 acc[4];
#pragma unroll
    for (int j = 0; j < 4; ++j) acc[j] = __float2half2_rn(0.0f);

#pragma unroll
    for (int p = 0; p < 3; ++p) {
        float wside = fabsf(sbase - s.wx[p]);
        __half2 w0 = __float2half2_rn(wside * omwy);
        __half2 w1 = __float2half2_rn(wside * s.wy);
        const __half2* h0 = reinterpret_cast<const __half2*>(&s.r0[p]);
        const __half2* h1 = reinterpret_cast<const __half2*>(&s.r1[p]);
#pragma unroll
        for (int k = 0; k < 4; ++k) {
            acc[k] = __hfma2(h1[k], w1, acc[k]);
            acc[k] = __hfma2(h0[k], w0, acc[k]);
        }
    }

    // Merge x0-side (lanes 0-3) with x1-side (lanes 4-7) in half2.
#pragma unroll
    for (int j = 0; j < 4; ++j) {
        unsigned u = __shfl_xor_sync(0xffffffffu,
                                     *reinterpret_cast<const unsigned*>(&acc[j]), 4);
        acc[j] = __hadd2(acc[j], *reinterpret_cast<__half2*>(&u));
    }

    float2 fa = __half22float2(acc[side * 2 + 0]);
    float2 fb = __half22float2(acc[side * 2 + 1]);
    float* o = out + (size_t)pt * FEAT + (ln & 3) * 8 + side * 4;
    *reinterpret_cast<float4*>(o) = make_float4(fa.x, fa.y, fb.x, fb.y);
}

// ---------------------------------------------------------------------------
// Main: 2 points per 8-lane group; all 12 gathers pinned in-flight via
// volatile PTX loads before either consume (true MLP=12 per lane).
// ---------------------------------------------------------------------------
__global__ void __launch_bounds__(256)
kplanes_sample_kernel(const float4* __restrict__ inp, float* __restrict__ out) {
    int tid  = blockIdx.x * blockDim.x + threadIdx.x;
    int g    = tid >> 3;
    int ln   = tid & 7;
    int side = ln >> 2;
    float sbase = (float)(1 - side);
    unsigned lnoff = (unsigned)ln << 4;
    int pt0 = g * 2;
    if (pt0 >= NPTS) return;
    int pt1 = pt0 + 1;

    const char* gbase = reinterpret_cast<const char*>(g_pairs);

    float4 c0 = __ldg(inp + pt0);
    float4 c1 = __ldg(inp + pt1);

    PtState s0, s1;
    issue_point(c0, lnoff, gbase, s0);
    issue_point(c1, lnoff, gbase, s1);
    consume_point(s0, ln, side, sbase, out, pt0);
    consume_point(s1, ln, side, sbase, out, pt1);
}

extern "C" void kernel_launch(void* const* d_in, const int* in_sizes, int n_in,
                              void* d_out, int out_size) {
    const float* inp = (const float*)d_in[0];
    const float* p0  = (const float*)d_in[1];
    const float* p1  = (const float*)d_in[2];
    const float* p2  = (const float*)d_in[3];
    float* out = (float*)d_out;

    {
        int total = 3 * TEXELS;
        int threads = 256;
        int blocks = (total + threads - 1) / threads;
        build_pairs_kernel<<<blocks, threads>>>(p0, p1, p2);
    }
    {
        long long total = (long long)NPTS * 8 / 2;   // 8 lanes, 2 points/group
        int threads = 256;
        int blocks = (int)((total + threads - 1) / threads);
        kplanes_sample_kernel<<<blocks, threads>>>((const float4*)inp, out);
    }
}